// round 8
// baseline (speedup 1.0000x reference)
#include <cuda_runtime.h>

#define TBN 65536   // SEQ*B
#define DN  512
#define HN  128

typedef unsigned long long u64;

// ---------------- f32x2 packed-fp32 helpers (exact fp32 semantics) ----------------
__device__ __forceinline__ u64 ffma2(u64 a, u64 b, u64 c) {
    u64 d;
    asm("fma.rn.f32x2 %0, %1, %2, %3;" : "=l"(d) : "l"(a), "l"(b), "l"(c));
    return d;
}
__device__ __forceinline__ u64 dup2(float x) {
    u64 d; asm("mov.b64 %0, {%1, %1};" : "=l"(d) : "f"(x)); return d;
}
__device__ __forceinline__ u64 pack2(float x, float y) {
    u64 d; asm("mov.b64 %0, {%1, %2};" : "=l"(d) : "f"(x), "f"(y)); return d;
}
__device__ __forceinline__ float2 unpack2(u64 v) {
    float2 r; asm("mov.b64 {%0, %1}, %2;" : "=f"(r.x), "=f"(r.y) : "l"(v)); return r;
}

// ---------------- scratch (static __device__ — allocation-free) ----------------
// Rank-compacted K/V per (t,b): rank 0 = shared slot 0, rank 1/2 = routed top-1/top-2.
__device__ float g_K[(size_t)TBN * 384];
__device__ float g_V[(size_t)TBN * 384];
__device__ float g_Q[(size_t)TBN * 128];
__device__ float g_Wt[(size_t)TBN * 8];          // readout weight per routed slot (0 = inactive)
__device__ unsigned char g_Rk[(size_t)TBN * 8];  // rank (1 or 2) where active
__device__ int  g_list[8][TBN];                   // unordered gather lists (tb | rank<<20)
__device__ int  g_cnt[8];
__device__ int2 g_olist[8][16][4096];             // TIME-ORDERED per-(slot,b): {tb|rank<<20, w}
__device__ int  g_ocnt[8][16];
// Chunked-scan scratch: dM[slot][b][chunk][128*128] (ΔM, then overwritten with chunk-start M)
__device__ float g_dM[(size_t)9 * 16 * 8 * 16384];
// Per-rank output planes: disjoint writers (rank 0 = slot0, ranks 1/2 = routed top-1/2).
// Every element of every plane is written (top-2 always exists) -> no zero-init, no atomics.
__device__ float g_O[3][(size_t)TBN * HN];

// ---------------- gate: logits -> top2 -> weights, ranks, per-slot lists ----------------
__global__ __launch_bounds__(256) void gate_kernel(const float* __restrict__ X,
                                                   const float* __restrict__ Wg,
                                                   const float* __restrict__ bg) {
    const int warp = threadIdx.x >> 5;
    const int lane = threadIdx.x & 31;
    const int tb = blockIdx.x * 8 + warp;
    const float* x = X + (size_t)tb * DN;

    float acc[8];
#pragma unroll
    for (int n = 0; n < 8; n++) acc[n] = 0.f;
    for (int d = lane; d < DN; d += 32) {
        float xv = __ldg(x + d);
#pragma unroll
        for (int n = 0; n < 8; n++) acc[n] += xv * __ldg(Wg + n * DN + d);
    }
#pragma unroll
    for (int n = 0; n < 8; n++) {
#pragma unroll
        for (int o = 16; o > 0; o >>= 1)
            acc[n] += __shfl_xor_sync(0xffffffffu, acc[n], o);
    }

    if (lane == 0) {
        float l[8];
#pragma unroll
        for (int n = 0; n < 8; n++) l[n] = acc[n] + __ldg(bg + n);

        // softmax monotonic -> top-2 of logits; ties -> lowest index (jax.lax.top_k)
        int i1 = 0; float m1 = l[0];
#pragma unroll
        for (int n = 1; n < 8; n++) if (l[n] > m1) { m1 = l[n]; i1 = n; }
        int i2 = -1; float m2 = -3.402823466e38f;
#pragma unroll
        for (int n = 0; n < 8; n++) if (n != i1 && l[n] > m2) { m2 = l[n]; i2 = n; }

        float e  = expf(m2 - m1);            // renormalized top-2 weights
        float g1 = 1.f / (1.f + e);
        float g2 = e   / (1.f + e);

#pragma unroll
        for (int n = 0; n < 8; n++)
            g_Wt[(size_t)tb * 8 + n] = (n == i1) ? g1 : (n == i2) ? g2 : 0.f;
        g_Rk[(size_t)tb * 8 + i1] = 1;
        g_Rk[(size_t)tb * 8 + i2] = 2;

        int p1 = atomicAdd(&g_cnt[i1], 1);
        g_list[i1][p1] = tb | (1 << 20);
        int p2 = atomicAdd(&g_cnt[i2], 1);
        g_list[i2][p2] = tb | (2 << 20);
    }
}

// ---------------- ordered compaction: per (slot,b) time-sorted active list ----------------
__global__ void compact_kernel() {
    const int sl = blockIdx.x;   // 0..7 -> slot sl+1
    const int b  = blockIdx.y;
    const int lane = threadIdx.x;   // 32 threads
    int n = 0;
    for (int base = 0; base < 4096; base += 32) {
        int t = base + lane;
        int tb = t * 16 + b;
        float w = g_Wt[(size_t)tb * 8 + sl];
        int rk  = g_Rk[(size_t)tb * 8 + sl];
        bool act = (w != 0.f);
        unsigned mask = __ballot_sync(0xffffffffu, act);
        if (act) {
            int pos = n + __popc(mask & ((1u << lane) - 1u));
            g_olist[sl][b][pos] = make_int2(tb | (rk << 20), __float_as_int(w));
        }
        n += __popc(mask);
    }
    if (lane == 0) g_ocnt[sl][b] = n;
}

// ---------------- f32x2 GEMM core: C[128 x 128] = A_rows x W[128 x 512]^T + bias --------
// Plain smem; A row-pairs read directly as u64 (adjacent rows), B duplicated in regs.
// Ping-pong smem buffers: one barrier per k-tile. acc[p][j] = row pair (ty*8+2p,+2p+1)
// x col (tx*8+j). 2 CTAs/SM for cross-CTA latency cover.
struct GSmem {
    float As[2][16][132];
    float Bs[2][16][132];
    int aRow[128];       // global A row index per tile row
    int rOut[128];       // output base offset per tile row
};

__device__ __forceinline__ void gemm_core(const float* __restrict__ A,
                                          const float* __restrict__ W,
                                          const float* __restrict__ bias,
                                          float* __restrict__ out,
                                          GSmem& s) {
    const int tid = threadIdx.x;
    const int tx = tid & 15;
    const int ty = tid >> 4;

    // loader mapping: 4 threads per row, 2 phases cover 128 rows
    const int rA0 = tid >> 2;
    const int kq0 = (tid & 3) * 4;
    const int rA1 = (tid + 256) >> 2;
    const int kq1 = ((tid + 256) & 3) * 4;

    u64 acc[4][8];
#pragma unroll
    for (int p = 0; p < 4; p++)
#pragma unroll
        for (int j = 0; j < 8; j++) acc[p][j] = 0ull;

    const float* arow0 = A + (size_t)s.aRow[rA0] * DN;
    const float* arow1 = A + (size_t)s.aRow[rA1] * DN;
    const float* wrow0 = W + (size_t)rA0 * DN;
    const float* wrow1 = W + (size_t)rA1 * DN;

    // prefetch tile 0
    float4 pa0 = *(const float4*)(arow0 + kq0);
    float4 pb0 = *(const float4*)(wrow0 + kq0);
    float4 pa1 = *(const float4*)(arow1 + kq1);
    float4 pb1 = *(const float4*)(wrow1 + kq1);

#pragma unroll 1
    for (int t = 0; t < 32; t++) {
        const int buf = t & 1;
        // store tile t (safe: last readers of buf finished before the sync in t-1)
        s.As[buf][kq0 + 0][rA0] = pa0.x; s.As[buf][kq0 + 1][rA0] = pa0.y;
        s.As[buf][kq0 + 2][rA0] = pa0.z; s.As[buf][kq0 + 3][rA0] = pa0.w;
        s.Bs[buf][kq0 + 0][rA0] = pb0.x; s.Bs[buf][kq0 + 1][rA0] = pb0.y;
        s.Bs[buf][kq0 + 2][rA0] = pb0.z; s.Bs[buf][kq0 + 3][rA0] = pb0.w;
        s.As[buf][kq1 + 0][rA1] = pa1.x; s.As[buf][kq1 + 1][rA1] = pa1.y;
        s.As[buf][kq1 + 2][rA1] = pa1.z; s.As[buf][kq1 + 3][rA1] = pa1.w;
        s.Bs[buf][kq1 + 0][rA1] = pb1.x; s.Bs[buf][kq1 + 1][rA1] = pb1.y;
        s.Bs[buf][kq1 + 2][rA1] = pb1.z; s.Bs[buf][kq1 + 3][rA1] = pb1.w;
        __syncthreads();

        if (t + 1 < 32) {   // prefetch tile t+1; latency covered by compute below
            int ko = (t + 1) * 16;
            pa0 = *(const float4*)(arow0 + ko + kq0);
            pb0 = *(const float4*)(wrow0 + ko + kq0);
            pa1 = *(const float4*)(arow1 + ko + kq1);
            pb1 = *(const float4*)(wrow1 + ko + kq1);
        }

#pragma unroll
        for (int k = 0; k < 16; k++) {
            // A row-pairs as packed f32x2 directly from smem (rows adjacent)
            ulonglong2 a01 = *(const ulonglong2*)&s.As[buf][k][ty * 8];
            ulonglong2 a23 = *(const ulonglong2*)&s.As[buf][k][ty * 8 + 4];
            float4 b0 = *(const float4*)&s.Bs[buf][k][tx * 8];
            float4 b1 = *(const float4*)&s.Bs[buf][k][tx * 8 + 4];
            u64 A2[4] = {a01.x, a01.y, a23.x, a23.y};
            u64 B2[8] = {dup2(b0.x), dup2(b0.y), dup2(b0.z), dup2(b0.w),
                         dup2(b1.x), dup2(b1.y), dup2(b1.z), dup2(b1.w)};
#pragma unroll
            for (int p = 0; p < 4; p++)
#pragma unroll
                for (int j = 0; j < 8; j++) acc[p][j] = ffma2(A2[p], B2[j], acc[p][j]);
        }
    }

    const float4 bc0 = *(const float4*)(bias + tx * 8);
    const float4 bc1 = *(const float4*)(bias + tx * 8 + 4);
#pragma unroll
    for (int p = 0; p < 4; p++) {
        int r = ty * 8 + 2 * p;
        float2 u0 = unpack2(acc[p][0]), u1 = unpack2(acc[p][1]);
        float2 u2 = unpack2(acc[p][2]), u3 = unpack2(acc[p][3]);
        float2 u4 = unpack2(acc[p][4]), u5 = unpack2(acc[p][5]);
        float2 u6 = unpack2(acc[p][6]), u7 = unpack2(acc[p][7]);
        float* olo = out + s.rOut[r];
        float* ohi = out + s.rOut[r + 1];
        float4 vlo0 = {u0.x + bc0.x, u1.x + bc0.y, u2.x + bc0.z, u3.x + bc0.w};
        float4 vlo1 = {u4.x + bc1.x, u5.x + bc1.y, u6.x + bc1.z, u7.x + bc1.w};
        float4 vhi0 = {u0.y + bc0.x, u1.y + bc0.y, u2.y + bc0.z, u3.y + bc0.w};
        float4 vhi1 = {u4.y + bc1.x, u5.y + bc1.y, u6.y + bc1.z, u7.y + bc1.w};
        *(float4*)(olo + tx * 8)     = vlo0;
        *(float4*)(olo + tx * 8 + 4) = vlo1;
        *(float4*)(ohi + tx * 8)     = vhi0;
        *(float4*)(ohi + tx * 8 + 4) = vhi1;
    }
}

// Full GEMM over all tb rows (slot-0 K, slot-0 V, Q)
__global__ __launch_bounds__(256, 2) void gemm_full(const float* __restrict__ A,
                                                    const float* __restrict__ W,
                                                    const float* __restrict__ bias,
                                                    float* __restrict__ out, int ostride) {
    __shared__ GSmem s;
    int m0 = blockIdx.x * 128;
    if (threadIdx.x < 128) {
        s.aRow[threadIdx.x] = m0 + (int)threadIdx.x;
        s.rOut[threadIdx.x] = (m0 + (int)threadIdx.x) * ostride;
    }
    __syncthreads();
    gemm_core(A, W, bias, out, s);
}

// Gathered GEMM over the per-slot selected (t,b) lists (routed K and V)
__global__ __launch_bounds__(256, 2) void gemm_gather(const float* __restrict__ A,
                                                      const float* __restrict__ Wk,
                                                      const float* __restrict__ Wv,
                                                      const float* __restrict__ bk,
                                                      const float* __restrict__ bv,
                                                      float* __restrict__ outK,
                                                      float* __restrict__ outV) {
    const int sl = blockIdx.y;           // 0..7 -> slot sl+1
    const int kv = blockIdx.z;           // 0 = K, 1 = V
    const int count = g_cnt[sl];
    if ((int)blockIdx.x * 128 >= count) return;

    __shared__ GSmem s;
    if (threadIdx.x < 128) {
        int idx = (int)blockIdx.x * 128 + (int)threadIdx.x;
        if (idx >= count) idx = count - 1;       // duplicate rows write identical values
        int e = g_list[sl][idx];
        int tbr = e & 0xFFFFF;
        int rk  = e >> 20;
        s.aRow[threadIdx.x] = tbr;
        s.rOut[threadIdx.x] = tbr * 384 + rk * 128;
    }
    __syncthreads();
    const float* W    = (kv ? Wv : Wk) + (size_t)(sl + 1) * 128 * DN;
    const float* bias = (kv ? bv : bk) + (sl + 1) * 128;
    gemm_core(A, W, bias, kv ? outV : outK, s);
}

// ---------------- chunked scan: phase A (ΔM per chunk) ----------------
// Grid (9, 16, 16): slot, b, z = chunk*2 + colhalf. Thread: 2 cols (jA, jA+32) x 16 rows.
// slot 0: 8 chunks of 512 steps. routed: 4 chunks over the ordered active list.
__device__ __forceinline__ bool chunk_range(int slot, int b, int chunk,
                                            int& s0, int& s1, const int2*& lst) {
    if (slot == 0) { s0 = chunk * 512; s1 = s0 + 512; lst = nullptr; return true; }
    if (chunk >= 4) return false;
    int n = g_ocnt[slot - 1][b];
    int cs = (n + 3) >> 2;
    s0 = chunk * cs; s1 = min(n, s0 + cs);
    lst = g_olist[slot - 1][b];
    return s0 < s1;
}

__global__ __launch_bounds__(256) void deltaM_kernel() {
    const int slot = blockIdx.x, b = blockIdx.y;
    const int chunk = blockIdx.z >> 1, half = blockIdx.z & 1;
    int s0, s1; const int2* lst;
    if (!chunk_range(slot, b, chunk, s0, s1, lst)) return;

    const int tid = threadIdx.x;
    const int jA = half * 64 + (tid & 31);
    const int jB = jA + 32;
    const int r0 = (tid >> 5) * 16;

    u64 MA[8], MB[8];
#pragma unroll
    for (int m = 0; m < 8; m++) { MA[m] = 0ull; MB[m] = 0ull; }

    for (int i = s0; i < s1; i++) {
        int tb, rank;
        if (slot == 0) { tb = i * 16 + b; rank = 0; }
        else { int2 e = __ldg(&lst[i]); tb = e.x & 0xFFFFF; rank = (e.x >> 20) & 3; }
        size_t off = (size_t)tb * 384 + rank * 128;
        const float* kp = g_K + off + r0;
        u64 vA2 = dup2(__ldg(g_V + off + jA));
        u64 vB2 = dup2(__ldg(g_V + off + jB));
#pragma unroll
        for (int r = 0; r < 16; r += 4) {
            ulonglong2 kk = *(const ulonglong2*)(kp + r);
            MA[r / 2]     = ffma2(kk.x, vA2, MA[r / 2]);
            MA[r / 2 + 1] = ffma2(kk.y, vA2, MA[r / 2 + 1]);
            MB[r / 2]     = ffma2(kk.x, vB2, MB[r / 2]);
            MB[r / 2 + 1] = ffma2(kk.y, vB2, MB[r / 2 + 1]);
        }
    }

    float* dm = g_dM + (((size_t)(slot * 16 + b) * 8 + chunk) * 16384);
#pragma unroll
    for (int r = 0; r < 16; r += 2) {
        float2 a = unpack2(MA[r / 2]);
        float2 c = unpack2(MB[r / 2]);
        dm[(r0 + r) * 128 + jA]     = a.x;
        dm[(r0 + r + 1) * 128 + jA] = a.y;
        dm[(r0 + r) * 128 + jB]     = c.x;
        dm[(r0 + r + 1) * 128 + jB] = c.y;
    }
}

// ---------------- phase B: exclusive prefix over chunks (dM -> chunk-start M) ----------
__global__ __launch_bounds__(256) void prefixM_kernel(const float* __restrict__ M0) {
    const int slot = blockIdx.x, b = blockIdx.y;
    const int nch = (slot == 0) ? 8 : 4;
    float4* __restrict__ base = (float4*)(g_dM + ((size_t)(slot * 16 + b) * 8) * 16384);
    const float4* __restrict__ m0 = (const float4*)M0;
    for (int e = threadIdx.x; e < 4096; e += 512) {
        const int e2 = e + 256;
        float4 acc  = __ldg(m0 + e);
        float4 acc2 = __ldg(m0 + e2);
        for (int c = 0; c < nch; c++) {
            float4 t  = base[c * 4096 + e];
            float4 t2 = base[c * 4096 + e2];
            base[c * 4096 + e]  = acc;    // exclusive prefix = M at chunk start
            base[c * 4096 + e2] = acc2;
            acc.x  += t.x;  acc.y  += t.y;  acc.z  += t.z;  acc.w  += t.w;
            acc2.x += t2.x; acc2.y += t2.y; acc2.z += t2.z; acc2.w += t2.w;
        }
    }
}

// ---------------- phase C: scan within chunk + weighted readout (NO atomics) ----------
// Each (tb, j, rank) cell has exactly one writer block -> plain stores into g_O[rank].
__global__ __launch_bounds__(256) void scanM_kernel() {
    const int slot = blockIdx.x, b = blockIdx.y;
    const int chunk = blockIdx.z >> 1, half = blockIdx.z & 1;
    int s0, s1; const int2* lst;
    if (!chunk_range(slot, b, chunk, s0, s1, lst)) return;

    const int tid = threadIdx.x;
    const int jA = half * 64 + (tid & 31);
    const int jB = jA + 32;
    const int r0 = (tid >> 5) * 16;

    const float* dm = g_dM + (((size_t)(slot * 16 + b) * 8 + chunk) * 16384);
    u64 MA[8], MB[8];
#pragma unroll
    for (int r = 0; r < 16; r += 2) {
        MA[r / 2] = pack2(dm[(r0 + r) * 128 + jA], dm[(r0 + r + 1) * 128 + jA]);
        MB[r / 2] = pack2(dm[(r0 + r) * 128 + jB], dm[(r0 + r + 1) * 128 + jB]);
    }

#pragma unroll 2
    for (int i = s0; i < s1; i++) {
        int tb, rank; float w;
        if (slot == 0) { tb = i * 16 + b; rank = 0; w = 1.f; }
        else {
            int2 e = __ldg(&lst[i]);
            tb = e.x & 0xFFFFF; rank = (e.x >> 20) & 3; w = __int_as_float(e.y);
        }
        size_t off = (size_t)tb * 384 + rank * 128;
        const float* kp = g_K + off + r0;
        const float* qp = g_Q + (size_t)tb * 128 + r0;
        u64 vA2 = dup2(__ldg(g_V + off + jA));
        u64 vB2 = dup2(__ldg(g_V + off + jB));

        u64 aA0 = 0ull, aA1 = 0ull, aB0 = 0ull, aB1 = 0ull;
#pragma unroll
        for (int r = 0; r < 16; r += 4) {
            ulonglong2 kk = *(const ulonglong2*)(kp + r);
            ulonglong2 qq = *(const ulonglong2*)(qp + r);
            MA[r / 2]     = ffma2(kk.x, vA2, MA[r / 2]);
            MA[r / 2 + 1] = ffma2(kk.y, vA2, MA[r / 2 + 1]);
            aA0 = ffma2(qq.x, MA[r / 2], aA0);
            aA1 = ffma2(qq.y, MA[r / 2 + 1], aA1);
            MB[r / 2]     = ffma2(kk.x, vB2, MB[r / 2]);
            MB[r / 2 + 1] = ffma2(kk.y, vB2, MB[r / 2 + 1]);
            aB0 = ffma2(qq.x, MB[r / 2], aB0);
            aB1 = ffma2(qq.y, MB[r / 2 + 1], aB1);
        }
        // partial over this thread's 16 rows; 8 warps (r0 groups) combine via the
        // per-rank plane? No -- each warp covers DIFFERENT rows of the q-dot, so the
        // 8 r0-groups must sum. Do it in smem-free fashion: warp-stride atomicity
        // avoided by having each r0 group write to a distinct row-block accumulator
        // is wrong; instead reduce across the 8 groups via shared memory.
        __shared__ float red[2][256];
        float2 sA0 = unpack2(aA0), sA1 = unpack2(aA1);
        float2 sB0 = unpack2(aB0), sB1 = unpack2(aB1);
        red[0][tid] = (sA0.x + sA0.y) + (sA1.x + sA1.y);
        red[1][tid] = (sB0.x + sB0.y) + (sB1.x + sB1.y);
        __syncthreads();
        if (tid < 32) {
            float sa = 0.f, sb = 0.f;
#pragma unroll
            for (int gsel = 0; gsel < 8; gsel++) {
                sa += red[0][gsel * 32 + tid];
                sb += red[1][gsel * 32 + tid];
            }
            g_O[rank][(size_t)tb * HN + jA] = w * sa;
            g_O[rank][(size_t)tb * HN + jB] = w * sb;
        }
        __syncthreads();
    }
}

// ---------------- fuse: out = sum of 3 rank planes ----------------
__global__ __launch_bounds__(256) void fuse_kernel(float* __restrict__ out) {
    size_t i = (size_t)blockIdx.x * 256 + threadIdx.x;   // float4 index
    const float4* p0 = (const float4*)g_O[0];
    const float4* p1 = (const float4*)g_O[1];
    const float4* p2 = (const float4*)g_O[2];
    float4 a = __ldg(p0 + i), b = __ldg(p1 + i), c = __ldg(p2 + i);
    float4 r = {a.x + b.x + c.x, a.y + b.y + c.y, a.z + b.z + c.z, a.w + b.w + c.w};
    ((float4*)out)[i] = r;
}

// ---------------- launcher ----------------
extern "C" void kernel_launch(void* const* d_in, const int* in_sizes, int n_in,
                              void* d_out, int out_size) {
    const float* X  = (const float*)d_in[0];
    const float* M0 = (const float*)d_in[1];
    const float* Wk = (const float*)d_in[2];
    const float* bk = (const float*)d_in[3];
    const float* Wv = (const float*)d_in[4];
    const float* bv = (const float*)d_in[5];
    const float* Wg = (const float*)d_in[6];
    const float* bg = (const float*)d_in[7];
    const float* Wq = (const float*)d_in[8];
    const float* bq = (const float*)d_in[9];
    float* out = (float*)d_out;

    float *pK, *pV, *pQ; int* pCnt;
    cudaGetSymbolAddress((void**)&pK, g_K);
    cudaGetSymbolAddress((void**)&pV, g_V);
    cudaGetSymbolAddress((void**)&pQ, g_Q);
    cudaGetSymbolAddress((void**)&pCnt, g_cnt);

    cudaMemsetAsync(pCnt, 0, 8 * sizeof(int));

    gate_kernel<<<TBN / 8, 256>>>(X, Wg, bg);
    compact_kernel<<<dim3(8, 16), 32>>>();
    gemm_full<<<TBN / 128, 256>>>(X, Wk, bk, pK, 384);   // slot-0 K -> rank 0
    gemm_full<<<TBN / 128, 256>>>(X, Wv, bv, pV, 384);   // slot-0 V -> rank 0
    gemm_full<<<TBN / 128, 256>>>(X, Wq, bq, pQ, 128);   // Q
    gemm_gather<<<dim3(512, 8, 2), 256>>>(X, Wk, Wv, bk, bv, pK, pV);
    deltaM_kernel<<<dim3(9, 16, 16), 256>>>();
    prefixM_kernel<<<dim3(9, 16), 256>>>(M0);
    scanM_kernel<<<dim3(9, 16, 16), 256>>>();
    fuse_kernel<<<TBN * HN / 4 / 256, 256>>>(out);
}

// round 10
// speedup vs baseline: 1.4768x; 1.4768x over previous
#include <cuda_runtime.h>

#define TBN 65536   // SEQ*B
#define DN  512
#define HN  128

typedef unsigned long long u64;

// ---------------- f32x2 packed-fp32 helpers (exact fp32 semantics) ----------------
__device__ __forceinline__ u64 ffma2(u64 a, u64 b, u64 c) {
    u64 d;
    asm("fma.rn.f32x2 %0, %1, %2, %3;" : "=l"(d) : "l"(a), "l"(b), "l"(c));
    return d;
}
__device__ __forceinline__ u64 dup2(float x) {
    u64 d; asm("mov.b64 %0, {%1, %1};" : "=l"(d) : "f"(x)); return d;
}
__device__ __forceinline__ float2 unpack2(u64 v) {
    float2 r; asm("mov.b64 {%0, %1}, %2;" : "=f"(r.x), "=f"(r.y) : "l"(v)); return r;
}

// ---------------- scratch (static __device__ — allocation-free) ----------------
__device__ float g_K[(size_t)TBN * 384];          // rank-compacted keys
__device__ float g_V[(size_t)TBN * 384];
__device__ float g_Q[(size_t)TBN * 128];
__device__ float g_Wt[(size_t)TBN * 8];
__device__ unsigned char g_Rk[(size_t)TBN * 8];
__device__ int  g_list[8][TBN];                    // unordered gather lists (tb | rank<<20)
__device__ int  g_cnt[8];
__device__ int2 g_olist[8][16][4096];              // time-ordered per-(slot,b) lists
__device__ int  g_ocnt[8][16];
// chunk scratch: [slot][b][chunk<32][128x128]
__device__ float g_dM[(size_t)9 * 16 * 32 * 16384];   // ΔM then chunk-start M
__device__ float g_S [(size_t)9 * 16 * 32 * 16384];   // masked S = tril(Q K^T), natural [i][j]
__device__ float g_O [(size_t)3 * TBN * 128];         // per-rank output planes (disjoint writers)

// ---------------- gate ----------------
__global__ __launch_bounds__(256) void gate_kernel(const float* __restrict__ X,
                                                   const float* __restrict__ Wg,
                                                   const float* __restrict__ bg) {
    const int warp = threadIdx.x >> 5;
    const int lane = threadIdx.x & 31;
    const int tb = blockIdx.x * 8 + warp;
    const float* x = X + (size_t)tb * DN;

    float acc[8];
#pragma unroll
    for (int n = 0; n < 8; n++) acc[n] = 0.f;
    for (int d = lane; d < DN; d += 32) {
        float xv = __ldg(x + d);
#pragma unroll
        for (int n = 0; n < 8; n++) acc[n] += xv * __ldg(Wg + n * DN + d);
    }
#pragma unroll
    for (int n = 0; n < 8; n++) {
#pragma unroll
        for (int o = 16; o > 0; o >>= 1)
            acc[n] += __shfl_xor_sync(0xffffffffu, acc[n], o);
    }

    if (lane == 0) {
        float l[8];
#pragma unroll
        for (int n = 0; n < 8; n++) l[n] = acc[n] + __ldg(bg + n);

        // softmax monotonic -> top-2 of logits; ties -> lowest index (jax.lax.top_k)
        int i1 = 0; float m1 = l[0];
#pragma unroll
        for (int n = 1; n < 8; n++) if (l[n] > m1) { m1 = l[n]; i1 = n; }
        int i2 = -1; float m2 = -3.402823466e38f;
#pragma unroll
        for (int n = 0; n < 8; n++) if (n != i1 && l[n] > m2) { m2 = l[n]; i2 = n; }

        float e  = expf(m2 - m1);
        float g1 = 1.f / (1.f + e);
        float g2 = e   / (1.f + e);

#pragma unroll
        for (int n = 0; n < 8; n++)
            g_Wt[(size_t)tb * 8 + n] = (n == i1) ? g1 : (n == i2) ? g2 : 0.f;
        g_Rk[(size_t)tb * 8 + i1] = 1;
        g_Rk[(size_t)tb * 8 + i2] = 2;

        int p1 = atomicAdd(&g_cnt[i1], 1);
        g_list[i1][p1] = tb | (1 << 20);
        int p2 = atomicAdd(&g_cnt[i2], 1);
        g_list[i2][p2] = tb | (2 << 20);
    }
}

// ---------------- ordered compaction ----------------
__global__ void compact_kernel() {
    const int sl = blockIdx.x;
    const int b  = blockIdx.y;
    const int lane = threadIdx.x;
    int n = 0;
    for (int base = 0; base < 4096; base += 32) {
        int t = base + lane;
        int tb = t * 16 + b;
        float w = g_Wt[(size_t)tb * 8 + sl];
        int rk  = g_Rk[(size_t)tb * 8 + sl];
        bool act = (w != 0.f);
        unsigned mask = __ballot_sync(0xffffffffu, act);
        if (act) {
            int pos = n + __popc(mask & ((1u << lane) - 1u));
            g_olist[sl][b][pos] = make_int2(tb | (rk << 20), __float_as_int(w));
        }
        n += __popc(mask);
    }
    if (lane == 0) g_ocnt[sl][b] = n;
}

// ---------------- projection GEMM core (inner = 512) ----------------
struct GSmem {
    float As[2][16][132];
    float Bs[2][16][132];
    int aRow[128];
    int rOut[128];
};

__device__ __forceinline__ void gemm_core(const float* __restrict__ A,
                                          const float* __restrict__ W,
                                          const float* __restrict__ bias,
                                          float* __restrict__ out,
                                          GSmem& s) {
    const int tid = threadIdx.x;
    const int tx = tid & 15;
    const int ty = tid >> 4;
    const int rA0 = tid >> 2;
    const int kq0 = (tid & 3) * 4;
    const int rA1 = 64 + rA0;

    u64 acc[4][8];
#pragma unroll
    for (int p = 0; p < 4; p++)
#pragma unroll
        for (int j = 0; j < 8; j++) acc[p][j] = 0ull;

    const float* arow0 = A + (size_t)s.aRow[rA0] * DN;
    const float* arow1 = A + (size_t)s.aRow[rA1] * DN;
    const float* wrow0 = W + (size_t)rA0 * DN;
    const float* wrow1 = W + (size_t)rA1 * DN;

    float4 pa0 = *(const float4*)(arow0 + kq0);
    float4 pb0 = *(const float4*)(wrow0 + kq0);
    float4 pa1 = *(const float4*)(arow1 + kq0);
    float4 pb1 = *(const float4*)(wrow1 + kq0);

#pragma unroll 1
    for (int t = 0; t < 32; t++) {
        const int buf = t & 1;
        s.As[buf][kq0 + 0][rA0] = pa0.x; s.As[buf][kq0 + 1][rA0] = pa0.y;
        s.As[buf][kq0 + 2][rA0] = pa0.z; s.As[buf][kq0 + 3][rA0] = pa0.w;
        s.Bs[buf][kq0 + 0][rA0] = pb0.x; s.Bs[buf][kq0 + 1][rA0] = pb0.y;
        s.Bs[buf][kq0 + 2][rA0] = pb0.z; s.Bs[buf][kq0 + 3][rA0] = pb0.w;
        s.As[buf][kq0 + 0][rA1] = pa1.x; s.As[buf][kq0 + 1][rA1] = pa1.y;
        s.As[buf][kq0 + 2][rA1] = pa1.z; s.As[buf][kq0 + 3][rA1] = pa1.w;
        s.Bs[buf][kq0 + 0][rA1] = pb1.x; s.Bs[buf][kq0 + 1][rA1] = pb1.y;
        s.Bs[buf][kq0 + 2][rA1] = pb1.z; s.Bs[buf][kq0 + 3][rA1] = pb1.w;
        __syncthreads();

        if (t + 1 < 32) {
            int ko = (t + 1) * 16;
            pa0 = *(const float4*)(arow0 + ko + kq0);
            pb0 = *(const float4*)(wrow0 + ko + kq0);
            pa1 = *(const float4*)(arow1 + ko + kq0);
            pb1 = *(const float4*)(wrow1 + ko + kq0);
        }

#pragma unroll
        for (int k = 0; k < 16; k++) {
            ulonglong2 a01 = *(const ulonglong2*)&s.As[buf][k][ty * 8];
            ulonglong2 a23 = *(const ulonglong2*)&s.As[buf][k][ty * 8 + 4];
            float4 b0 = *(const float4*)&s.Bs[buf][k][tx * 8];
            float4 b1 = *(const float4*)&s.Bs[buf][k][tx * 8 + 4];
            u64 A2[4] = {a01.x, a01.y, a23.x, a23.y};
            u64 B2[8] = {dup2(b0.x), dup2(b0.y), dup2(b0.z), dup2(b0.w),
                         dup2(b1.x), dup2(b1.y), dup2(b1.z), dup2(b1.w)};
#pragma unroll
            for (int p = 0; p < 4; p++)
#pragma unroll
                for (int j = 0; j < 8; j++) acc[p][j] = ffma2(A2[p], B2[j], acc[p][j]);
        }
    }

    const float4 bc0 = *(const float4*)(bias + tx * 8);
    const float4 bc1 = *(const float4*)(bias + tx * 8 + 4);
#pragma unroll
    for (int p = 0; p < 4; p++) {
        int r = ty * 8 + 2 * p;
        float2 u0 = unpack2(acc[p][0]), u1 = unpack2(acc[p][1]);
        float2 u2 = unpack2(acc[p][2]), u3 = unpack2(acc[p][3]);
        float2 u4 = unpack2(acc[p][4]), u5 = unpack2(acc[p][5]);
        float2 u6 = unpack2(acc[p][6]), u7 = unpack2(acc[p][7]);
        float* olo = out + s.rOut[r];
        float* ohi = out + s.rOut[r + 1];
        float4 vlo0 = {u0.x + bc0.x, u1.x + bc0.y, u2.x + bc0.z, u3.x + bc0.w};
        float4 vlo1 = {u4.x + bc1.x, u5.x + bc1.y, u6.x + bc1.z, u7.x + bc1.w};
        float4 vhi0 = {u0.y + bc0.x, u1.y + bc0.y, u2.y + bc0.z, u3.y + bc0.w};
        float4 vhi1 = {u4.y + bc1.x, u5.y + bc1.y, u6.y + bc1.z, u7.y + bc1.w};
        *(float4*)(olo + tx * 8)     = vlo0;
        *(float4*)(olo + tx * 8 + 4) = vlo1;
        *(float4*)(ohi + tx * 8)     = vhi0;
        *(float4*)(ohi + tx * 8 + 4) = vhi1;
    }
}

__global__ __launch_bounds__(256, 2) void gemm_full(const float* __restrict__ A,
                                                    const float* __restrict__ W,
                                                    const float* __restrict__ bias,
                                                    float* __restrict__ out, int ostride) {
    __shared__ GSmem s;
    int m0 = blockIdx.x * 128;
    if (threadIdx.x < 128) {
        s.aRow[threadIdx.x] = m0 + (int)threadIdx.x;
        s.rOut[threadIdx.x] = (m0 + (int)threadIdx.x) * ostride;
    }
    __syncthreads();
    gemm_core(A, W, bias, out, s);
}

__global__ __launch_bounds__(256, 2) void gemm_gather(const float* __restrict__ A,
                                                      const float* __restrict__ Wk,
                                                      const float* __restrict__ Wv,
                                                      const float* __restrict__ bk,
                                                      const float* __restrict__ bv,
                                                      float* __restrict__ outK,
                                                      float* __restrict__ outV) {
    const int sl = blockIdx.y;
    const int kv = blockIdx.z;
    const int count = g_cnt[sl];
    if ((int)blockIdx.x * 128 >= count) return;

    __shared__ GSmem s;
    if (threadIdx.x < 128) {
        int idx = (int)blockIdx.x * 128 + (int)threadIdx.x;
        if (idx >= count) idx = count - 1;       // duplicate rows write identical values
        int e = g_list[sl][idx];
        int tbr = e & 0xFFFFF;
        int rk  = e >> 20;
        s.aRow[threadIdx.x] = tbr;
        s.rOut[threadIdx.x] = tbr * 384 + rk * 128;
    }
    __syncthreads();
    const float* W    = (kv ? Wv : Wk) + (size_t)(sl + 1) * 128 * DN;
    const float* bias = (kv ? bv : bk) + (sl + 1) * 128;
    gemm_core(A, W, bias, kv ? outV : outK, s);
}

// ================= chunked linear attention: all GEMMs =================
// Chunk = 128 consecutive entries of the (slot,b) active list (slot0: identity list).
// o_i = w_i * ( q_i . M_start + sum_{j<=i} (q_i . k_j) v_j )

struct ChunkMap {
    int koff[128];   // offset into g_K/g_V (tb*384 + rank*128)
    int qoff[128];   // offset into g_Q (tb*128)
    int ooff[128];   // offset into g_O (rank*TBN*128 + tb*128)
    float w[128];
    int val[128];
};

__device__ __forceinline__ int num_chunks(int slot, int b) {
    return (slot == 0) ? 32 : ((g_ocnt[slot - 1][b] + 127) >> 7);
}

__device__ __forceinline__ void build_map(int slot, int b, int chunk, ChunkMap& m) {
    int tid = threadIdx.x;
    if (tid < 128) {
        int gi = chunk * 128 + tid;
        if (slot == 0) {
            int tb = gi * 16 + b;
            m.koff[tid] = tb * 384;
            m.qoff[tid] = tb * 128;
            m.ooff[tid] = tb * 128;       // rank 0 plane
            m.w[tid]   = 1.f;
            m.val[tid] = 1;
        } else {
            int n = g_ocnt[slot - 1][b];   // only called when chunk < num_chunks => n > 0
            int ci = min(gi, n - 1);
            int2 e = g_olist[slot - 1][b][ci];
            int tb = e.x & 0xFFFFF;
            int rk = (e.x >> 20) & 3;
            m.koff[tid] = tb * 384 + rk * 128;
            m.qoff[tid] = tb * 128;
            m.ooff[tid] = rk * (TBN * 128) + tb * 128;
            m.w[tid]   = __int_as_float(e.y);
            m.val[tid] = (gi < n) ? 1 : 0;
        }
    }
}

__device__ __forceinline__ size_t chunk_base(int slot, int b, int chunk) {
    return ((size_t)((slot * 16 + b) * 32 + chunk)) * 16384;
}

// ---- K1: dM_chunk = K_c^T V_c  (inner = 128 steps; pad steps have K zeroed) ----
__global__ __launch_bounds__(256, 2) void chunk_kv_kernel() {
    const int slot = blockIdx.x, b = blockIdx.y, chunk = blockIdx.z;
    if (chunk >= num_chunks(slot, b)) return;
    __shared__ ChunkMap m;
    __shared__ float Ks[2][16][132], Vs[2][16][132];
    build_map(slot, b, chunk, m);
    __syncthreads();

    const int tid = threadIdx.x;
    const int sl = tid >> 4, seg = tid & 15;   // loader: step-in-tile, 8-float segment
    const int tx = tid & 15, ty = tid >> 4;

    u64 acc[4][8];
#pragma unroll
    for (int p = 0; p < 4; p++)
#pragma unroll
        for (int j = 0; j < 8; j++) acc[p][j] = 0ull;

    float4 pk0, pk1, pv0, pv1;
    {
        int off = m.koff[sl]; int v = m.val[sl];
        const float* kp = g_K + off; const float* vp = g_V + off;
        float4 z = {0.f, 0.f, 0.f, 0.f};
        pk0 = v ? *(const float4*)(kp + seg * 8)     : z;
        pk1 = v ? *(const float4*)(kp + seg * 8 + 4) : z;
        pv0 = *(const float4*)(vp + seg * 8);
        pv1 = *(const float4*)(vp + seg * 8 + 4);
    }

#pragma unroll 1
    for (int t = 0; t < 8; t++) {
        const int buf = t & 1;
        *(float4*)&Ks[buf][sl][seg * 8]     = pk0;
        *(float4*)&Ks[buf][sl][seg * 8 + 4] = pk1;
        *(float4*)&Vs[buf][sl][seg * 8]     = pv0;
        *(float4*)&Vs[buf][sl][seg * 8 + 4] = pv1;
        __syncthreads();
        if (t + 1 < 8) {
            int idx = (t + 1) * 16 + sl;
            int off = m.koff[idx]; int v = m.val[idx];
            const float* kp = g_K + off; const float* vp = g_V + off;
            float4 z = {0.f, 0.f, 0.f, 0.f};
            pk0 = v ? *(const float4*)(kp + seg * 8)     : z;
            pk1 = v ? *(const float4*)(kp + seg * 8 + 4) : z;
            pv0 = *(const float4*)(vp + seg * 8);
            pv1 = *(const float4*)(vp + seg * 8 + 4);
        }
#pragma unroll
        for (int k = 0; k < 16; k++) {
            ulonglong2 a01 = *(const ulonglong2*)&Ks[buf][k][ty * 8];
            ulonglong2 a23 = *(const ulonglong2*)&Ks[buf][k][ty * 8 + 4];
            float4 b0 = *(const float4*)&Vs[buf][k][tx * 8];
            float4 b1 = *(const float4*)&Vs[buf][k][tx * 8 + 4];
            u64 A2[4] = {a01.x, a01.y, a23.x, a23.y};
            u64 B2[8] = {dup2(b0.x), dup2(b0.y), dup2(b0.z), dup2(b0.w),
                         dup2(b1.x), dup2(b1.y), dup2(b1.z), dup2(b1.w)};
#pragma unroll
            for (int p = 0; p < 4; p++)
#pragma unroll
                for (int j = 0; j < 8; j++) acc[p][j] = ffma2(A2[p], B2[j], acc[p][j]);
        }
        __syncthreads();
    }

    float* dm = g_dM + chunk_base(slot, b, chunk);
#pragma unroll
    for (int p = 0; p < 4; p++) {
        int r = ty * 8 + 2 * p;
        float2 u0 = unpack2(acc[p][0]), u1 = unpack2(acc[p][1]);
        float2 u2 = unpack2(acc[p][2]), u3 = unpack2(acc[p][3]);
        float2 u4 = unpack2(acc[p][4]), u5 = unpack2(acc[p][5]);
        float2 u6 = unpack2(acc[p][6]), u7 = unpack2(acc[p][7]);
        float4 lo0 = {u0.x, u1.x, u2.x, u3.x}, lo1 = {u4.x, u5.x, u6.x, u7.x};
        float4 hi0 = {u0.y, u1.y, u2.y, u3.y}, hi1 = {u4.y, u5.y, u6.y, u7.y};
        *(float4*)(dm + r * 128 + tx * 8)           = lo0;
        *(float4*)(dm + r * 128 + tx * 8 + 4)       = lo1;
        *(float4*)(dm + (r + 1) * 128 + tx * 8)     = hi0;
        *(float4*)(dm + (r + 1) * 128 + tx * 8 + 4) = hi1;
    }
}

// ---- prefix over chunks: dM -> chunk-start M (exclusive, seeded with M0) ----
__global__ __launch_bounds__(256) void prefixM_kernel(const float* __restrict__ M0) {
    const int slot = blockIdx.x, b = blockIdx.y;
    const int nch = num_chunks(slot, b);
    if (nch == 0) return;
    float4* __restrict__ base = (float4*)(g_dM + chunk_base(slot, b, 0));
    const float4* __restrict__ m0 = (const float4*)M0;
    const int e  = blockIdx.z * 512 + threadIdx.x;
    const int e2 = e + 256;
    float4 acc  = __ldg(m0 + e);
    float4 acc2 = __ldg(m0 + e2);
    for (int c = 0; c < nch; c++) {
        float4 t  = base[c * 4096 + e];
        float4 t2 = base[c * 4096 + e2];
        base[c * 4096 + e]  = acc;
        base[c * 4096 + e2] = acc2;
        acc.x  += t.x;  acc.y  += t.y;  acc.z  += t.z;  acc.w  += t.w;
        acc2.x += t2.x; acc2.y += t2.y; acc2.z += t2.z; acc2.w += t2.w;
    }
}

// ---- K2a: S_c = tril(Q_c K_c^T), stored natural [i][j] (inner = 128 hid) ----
__global__ __launch_bounds__(256, 2) void chunk_s_kernel() {
    const int slot = blockIdx.x, b = blockIdx.y, chunk = blockIdx.z;
    if (chunk >= num_chunks(slot, b)) return;
    __shared__ ChunkMap m;
    __shared__ float Qs[2][16][132], Kjs[2][16][132];
    build_map(slot, b, chunk, m);
    __syncthreads();

    const int tid = threadIdx.x;
    const int tx = tid & 15, ty = tid >> 4;
    const int rA0 = tid >> 2, kq0 = (tid & 3) * 4;
    const int rA1 = 64 + rA0;

    u64 acc[4][8];
#pragma unroll
    for (int p = 0; p < 4; p++)
#pragma unroll
        for (int j = 0; j < 8; j++) acc[p][j] = 0ull;

    float4 z = {0.f, 0.f, 0.f, 0.f};
    float4 pq0 = *(const float4*)(g_Q + m.qoff[rA0] + kq0);
    float4 pq1 = *(const float4*)(g_Q + m.qoff[rA1] + kq0);
    float4 pk0 = m.val[rA0] ? *(const float4*)(g_K + m.koff[rA0] + kq0) : z;
    float4 pk1 = m.val[rA1] ? *(const float4*)(g_K + m.koff[rA1] + kq0) : z;

#pragma unroll 1
    for (int t = 0; t < 8; t++) {
        const int buf = t & 1;
        Qs[buf][kq0 + 0][rA0] = pq0.x; Qs[buf][kq0 + 1][rA0] = pq0.y;
        Qs[buf][kq0 + 2][rA0] = pq0.z; Qs[buf][kq0 + 3][rA0] = pq0.w;
        Qs[buf][kq0 + 0][rA1] = pq1.x; Qs[buf][kq0 + 1][rA1] = pq1.y;
        Qs[buf][kq0 + 2][rA1] = pq1.z; Qs[buf][kq0 + 3][rA1] = pq1.w;
        Kjs[buf][kq0 + 0][rA0] = pk0.x; Kjs[buf][kq0 + 1][rA0] = pk0.y;
        Kjs[buf][kq0 + 2][rA0] = pk0.z; Kjs[buf][kq0 + 3][rA0] = pk0.w;
        Kjs[buf][kq0 + 0][rA1] = pk1.x; Kjs[buf][kq0 + 1][rA1] = pk1.y;
        Kjs[buf][kq0 + 2][rA1] = pk1.z; Kjs[buf][kq0 + 3][rA1] = pk1.w;
        __syncthreads();
        if (t + 1 < 8) {
            int ro = (t + 1) * 16 + kq0;
            pq0 = *(const float4*)(g_Q + m.qoff[rA0] + ro);
            pq1 = *(const float4*)(g_Q + m.qoff[rA1] + ro);
            pk0 = m.val[rA0] ? *(const float4*)(g_K + m.koff[rA0] + ro) : z;
            pk1 = m.val[rA1] ? *(const float4*)(g_K + m.koff[rA1] + ro) : z;
        }
#pragma unroll
        for (int k = 0; k < 16; k++) {
            ulonglong2 a01 = *(const ulonglong2*)&Qs[buf][k][ty * 8];
            ulonglong2 a23 = *(const ulonglong2*)&Qs[buf][k][ty * 8 + 4];
            float4 b0 = *(const float4*)&Kjs[buf][k][tx * 8];
            float4 b1 = *(const float4*)&Kjs[buf][k][tx * 8 + 4];
            u64 A2[4] = {a01.x, a01.y, a23.x, a23.y};
            u64 B2[8] = {dup2(b0.x), dup2(b0.y), dup2(b0.z), dup2(b0.w),
                         dup2(b1.x), dup2(b1.y), dup2(b1.z), dup2(b1.w)};
#pragma unroll
            for (int p = 0; p < 4; p++)
#pragma unroll
                for (int j = 0; j < 8; j++) acc[p][j] = ffma2(A2[p], B2[j], acc[p][j]);
        }
        __syncthreads();
    }

    float* S = g_S + chunk_base(slot, b, chunk);
#pragma unroll
    for (int p = 0; p < 4; p++) {
        int i0 = ty * 8 + 2 * p, i1 = i0 + 1;
        float rlo[8], rhi[8];
#pragma unroll
        for (int j = 0; j < 8; j++) {
            float2 u = unpack2(acc[p][j]);
            int jj = tx * 8 + j;
            rlo[j] = (jj <= i0) ? u.x : 0.f;   // causal mask (inclusive diagonal)
            rhi[j] = (jj <= i1) ? u.y : 0.f;
        }
        *(float4*)(S + i0 * 128 + tx * 8)     = *(float4*)&rlo[0];
        *(float4*)(S + i0 * 128 + tx * 8 + 4) = *(float4*)&rlo[4];
        *(float4*)(S + i1 * 128 + tx * 8)     = *(float4*)&rhi[0];
        *(float4*)(S + i1 * 128 + tx * 8 + 4) = *(float4*)&rhi[4];
    }
}

// ---- K2b: O_c = S_c V_c + Q_c M_start ; scale by w_i; store to rank plane ----
// inner = 256: tiles 0..7 (S + V), tiles 8..15 (Q + M_start)
__global__ __launch_bounds__(256, 2) void chunk_o_kernel() {
    const int slot = blockIdx.x, b = blockIdx.y, chunk = blockIdx.z;
    if (chunk >= num_chunks(slot, b)) return;
    __shared__ ChunkMap m;
    __shared__ float As[2][16][132], Bs[2][16][132];
    build_map(slot, b, chunk, m);
    __syncthreads();

    const int tid = threadIdx.x;
    const int tx = tid & 15, ty = tid >> 4;
    const int rA0 = tid >> 2, kq0 = (tid & 3) * 4;
    const int rA1 = 64 + rA0;
    const int sl = tid >> 4, seg = tid & 15;

    const float* S  = g_S  + chunk_base(slot, b, chunk);
    const float* dm = g_dM + chunk_base(slot, b, chunk);

    u64 acc[4][8];
#pragma unroll
    for (int p = 0; p < 4; p++)
#pragma unroll
        for (int j = 0; j < 8; j++) acc[p][j] = 0ull;

    float4 pa0, pa1, pb0, pb1;
    {
        pa0 = *(const float4*)(S + rA0 * 128 + kq0);
        pa1 = *(const float4*)(S + rA1 * 128 + kq0);
        const float* vp = g_V + m.koff[sl];     // pad steps: clamped-valid, masked by S=0
        pb0 = *(const float4*)(vp + seg * 8);
        pb1 = *(const float4*)(vp + seg * 8 + 4);
    }

#pragma unroll 1
    for (int t = 0; t < 16; t++) {
        const int buf = t & 1;
        As[buf][kq0 + 0][rA0] = pa0.x; As[buf][kq0 + 1][rA0] = pa0.y;
        As[buf][kq0 + 2][rA0] = pa0.z; As[buf][kq0 + 3][rA0] = pa0.w;
        As[buf][kq0 + 0][rA1] = pa1.x; As[buf][kq0 + 1][rA1] = pa1.y;
        As[buf][kq0 + 2][rA1] = pa1.z; As[buf][kq0 + 3][rA1] = pa1.w;
        *(float4*)&Bs[buf][sl][seg * 8]     = pb0;
        *(float4*)&Bs[buf][sl][seg * 8 + 4] = pb1;
        __syncthreads();
        if (t + 1 < 16) {
            int tn = t + 1;
            if (tn < 8) {
                pa0 = *(const float4*)(S + rA0 * 128 + tn * 16 + kq0);
                pa1 = *(const float4*)(S + rA1 * 128 + tn * 16 + kq0);
                const float* vp = g_V + m.koff[tn * 16 + sl];
                pb0 = *(const float4*)(vp + seg * 8);
                pb1 = *(const float4*)(vp + seg * 8 + 4);
            } else {
                int ro = (tn - 8) * 16;
                pa0 = *(const float4*)(g_Q + m.qoff[rA0] + ro + kq0);
                pa1 = *(const float4*)(g_Q + m.qoff[rA1] + ro + kq0);
                const float* mp = dm + (ro + sl) * 128;
                pb0 = *(const float4*)(mp + seg * 8);
                pb1 = *(const float4*)(mp + seg * 8 + 4);
            }
        }
#pragma unroll
        for (int k = 0; k < 16; k++) {
            ulonglong2 a01 = *(const ulonglong2*)&As[buf][k][ty * 8];
            ulonglong2 a23 = *(const ulonglong2*)&As[buf][k][ty * 8 + 4];
            float4 b0 = *(const float4*)&Bs[buf][k][tx * 8];
            float4 b1 = *(const float4*)&Bs[buf][k][tx * 8 + 4];
            u64 A2[4] = {a01.x, a01.y, a23.x, a23.y};
            u64 B2[8] = {dup2(b0.x), dup2(b0.y), dup2(b0.z), dup2(b0.w),
                         dup2(b1.x), dup2(b1.y), dup2(b1.z), dup2(b1.w)};
#pragma unroll
            for (int p = 0; p < 4; p++)
#pragma unroll
                for (int j = 0; j < 8; j++) acc[p][j] = ffma2(A2[p], B2[j], acc[p][j]);
        }
        __syncthreads();
    }

#pragma unroll
    for (int p = 0; p < 4; p++) {
        int i0 = ty * 8 + 2 * p, i1 = i0 + 1;
        float2 u0 = unpack2(acc[p][0]), u1 = unpack2(acc[p][1]);
        float2 u2 = unpack2(acc[p][2]), u3 = unpack2(acc[p][3]);
        float2 u4 = unpack2(acc[p][4]), u5 = unpack2(acc[p][5]);
        float2 u6 = unpack2(acc[p][6]), u7 = unpack2(acc[p][7]);
        if (m.val[i0]) {
            float w = m.w[i0];
            float* o = g_O + m.ooff[i0];
            float4 v0 = {w * u0.x, w * u1.x, w * u2.x, w * u3.x};
            float4 v1 = {w * u4.x, w * u5.x, w * u6.x, w * u7.x};
            *(float4*)(o + tx * 8)     = v0;
            *(float4*)(o + tx * 8 + 4) = v1;
        }
        if (m.val[i1]) {
            float w = m.w[i1];
            float* o = g_O + m.ooff[i1];
            float4 v0 = {w * u0.y, w * u1.y, w * u2.y, w * u3.y};
            float4 v1 = {w * u4.y, w * u5.y, w * u6.y, w * u7.y};
            *(float4*)(o + tx * 8)     = v0;
            *(float4*)(o + tx * 8 + 4) = v1;
        }
    }
}

// ---- fuse: out = sum of 3 rank planes ----
__global__ __launch_bounds__(256) void fuse_kernel(float* __restrict__ out) {
    size_t i = (size_t)blockIdx.x * 256 + threadIdx.x;
    const float4* p0 = (const float4*)(g_O);
    const float4* p1 = (const float4*)(g_O + (size_t)TBN * 128);
    const float4* p2 = (const float4*)(g_O + (size_t)2 * TBN * 128);
    float4 a = __ldg(p0 + i), b = __ldg(p1 + i), c = __ldg(p2 + i);
    float4 r = {a.x + b.x + c.x, a.y + b.y + c.y, a.z + b.z + c.z, a.w + b.w + c.w};
    ((float4*)out)[i] = r;
}

// ---------------- launcher ----------------
extern "C" void kernel_launch(void* const* d_in, const int* in_sizes, int n_in,
                              void* d_out, int out_size) {
    const float* X  = (const float*)d_in[0];
    const float* M0 = (const float*)d_in[1];
    const float* Wk = (const float*)d_in[2];
    const float* bk = (const float*)d_in[3];
    const float* Wv = (const float*)d_in[4];
    const float* bv = (const float*)d_in[5];
    const float* Wg = (const float*)d_in[6];
    const float* bg = (const float*)d_in[7];
    const float* Wq = (const float*)d_in[8];
    const float* bq = (const float*)d_in[9];
    float* out = (float*)d_out;

    float *pK, *pV, *pQ; int* pCnt;
    cudaGetSymbolAddress((void**)&pK, g_K);
    cudaGetSymbolAddress((void**)&pV, g_V);
    cudaGetSymbolAddress((void**)&pQ, g_Q);
    cudaGetSymbolAddress((void**)&pCnt, g_cnt);

    cudaMemsetAsync(pCnt, 0, 8 * sizeof(int));

    gate_kernel<<<TBN / 8, 256>>>(X, Wg, bg);
    compact_kernel<<<dim3(8, 16), 32>>>();
    gemm_full<<<TBN / 128, 256>>>(X, Wk, bk, pK, 384);
    gemm_full<<<TBN / 128, 256>>>(X, Wv, bv, pV, 384);
    gemm_full<<<TBN / 128, 256>>>(X, Wq, bq, pQ, 128);
    gemm_gather<<<dim3(512, 8, 2), 256>>>(X, Wk, Wv, bk, bv, pK, pV);
    chunk_kv_kernel<<<dim3(9, 16, 32), 256>>>();
    chunk_s_kernel<<<dim3(9, 16, 32), 256>>>();
    prefixM_kernel<<<dim3(9, 16, 8), 256>>>(M0);
    chunk_o_kernel<<<dim3(9, 16, 32), 256>>>();
    fuse_kernel<<<TBN * HN / 4 / 256, 256>>>(out);
}